// round 8
// baseline (speedup 1.0000x reference)
#include <cuda_runtime.h>
#include <math.h>

#define MAXN 50048
#define MAXE 1650080

// ------------ static device scratch (zero-initialized at load) -----------
__device__ float d_h1[MAXN * 64];
__device__ float d_as1[MAXN * 8];
__device__ float d_ad1[MAXN * 8];
__device__ float d_x1[MAXN * 64];
__device__ float d_as2[MAXN];
__device__ float d_ad2[MAXN];
__device__ float d_wsrc[64];
__device__ float d_wdst[64];
__device__ int   d_deg[MAXN];      // zero at load; k_scan re-zeroes after use
__device__ int   d_off[MAXN + 1];
__device__ int   d_cur[MAXN];
__device__ int   d_ssrc[MAXE];

// ---------------- hist (+ block0 computes wsrc/wdst = W2 @ att2) ----------
__global__ void k_hist(const int* __restrict__ ei, int E, int vec,
                       const float* __restrict__ W2,
                       const float* __restrict__ as2v, const float* __restrict__ ad2v) {
    if (blockIdx.x == 0 && threadIdx.x < 128) {
        int k = threadIdx.x & 63;
        const float* att = (threadIdx.x < 64) ? as2v : ad2v;
        float s = 0.f;
#pragma unroll 16
        for (int c = 0; c < 128; c++) s += W2[k * 128 + c] * att[c];
        if (threadIdx.x < 64) d_wsrc[k] = s;
        else                  d_wdst[k] = s;
    }
    int i = blockIdx.x * blockDim.x + threadIdx.x;
    int e = i * 4;
    if (e >= E) return;
    if (vec && e + 3 < E) {
        int4 d = *(const int4*)(ei + E + e);
        atomicAdd(&d_deg[d.x], 1);
        atomicAdd(&d_deg[d.y], 1);
        atomicAdd(&d_deg[d.z], 1);
        atomicAdd(&d_deg[d.w], 1);
    } else {
        for (int j = e; j < E && j < e + 4; j++)
            atomicAdd(&d_deg[ei[E + j]], 1);
    }
}

// single-block scan; places self loop at slot 0; re-zeroes d_deg
__global__ __launch_bounds__(1024) void k_scan(int n) {
    __shared__ int warpsum[32];
    int t = threadIdx.x, lane = t & 31, wid = t >> 5;
    int ipt = (n + 1023) >> 10;
    int start = t * ipt;
    int endi  = min(start + ipt, n);
    int s = 0;
    for (int i = start; i < endi; i++) s += d_deg[i] + 1;
    int incl = s;
#pragma unroll
    for (int o = 1; o < 32; o <<= 1) {
        int v = __shfl_up_sync(0xffffffffu, incl, o);
        if (lane >= o) incl += v;
    }
    if (lane == 31) warpsum[wid] = incl;
    __syncthreads();
    if (wid == 0) {
        int v = warpsum[lane];
        int wi = v;
#pragma unroll
        for (int o = 1; o < 32; o <<= 1) {
            int u = __shfl_up_sync(0xffffffffu, wi, o);
            if (lane >= o) wi += u;
        }
        warpsum[lane] = wi - v;
    }
    __syncthreads();
    int run = warpsum[wid] + (incl - s);
    for (int i = start; i < endi; i++) {
        int d = d_deg[i];
        d_deg[i] = 0;            // reset for next kernel_launch call
        d_off[i]  = run;
        d_ssrc[run] = i;
        d_cur[i]  = run + 1;
        run += d + 1;
    }
    if (t == 1023) d_off[n] = run;
}

// ------------- Fused Layer-1 GEMM + scatter (interleaved roles) -----------
__global__ __launch_bounds__(256) void k_gemm1_scatter(
    const float* __restrict__ x, const float* __restrict__ W1,
    const float* __restrict__ as, const float* __restrict__ ad, int n,
    const int* __restrict__ ei, int E, int vec)
{
    __shared__ float2 Ws[128 * 32];
    __shared__ float atts[64], attd[64];
    int t = threadIdx.x;

    if (blockIdx.x & 1) {
        int i = (blockIdx.x >> 1) * blockDim.x + t;
        int e = i * 4;
        if (e >= E) return;
        if (vec && e + 3 < E) {
            int4 s = *(const int4*)(ei + e);
            int4 d = *(const int4*)(ei + E + e);
            d_ssrc[atomicAdd(&d_cur[d.x], 1)] = s.x;
            d_ssrc[atomicAdd(&d_cur[d.y], 1)] = s.y;
            d_ssrc[atomicAdd(&d_cur[d.z], 1)] = s.z;
            d_ssrc[atomicAdd(&d_cur[d.w], 1)] = s.w;
        } else {
            for (int j = e; j < E && j < e + 4; j++)
                d_ssrc[atomicAdd(&d_cur[ei[E + j]], 1)] = ei[j];
        }
        return;
    }

    int w = t >> 5, l = t & 31;
    int nblk = gridDim.x >> 1;
    int bid  = blockIdx.x >> 1;
    const float2* Wv = (const float2*)W1;
    for (int i = t; i < 4096; i += 256) Ws[i] = Wv[i];
    if (t < 64) { atts[t] = as[t]; attd[t] = ad[t]; }
    __syncthreads();
    int ntiles = (n + 3) >> 2;
    for (int tile = bid * 8 + w; tile < ntiles; tile += nblk * 8) {
        int row0 = tile * 4;
        float xr[4][4];
#pragma unroll
        for (int r = 0; r < 4; r++) {
            const float* xp = x + (size_t)min(row0 + r, n - 1) * 128;
#pragma unroll
            for (int c = 0; c < 4; c++) xr[r][c] = xp[l + 32 * c];
        }
        float2 acc[4] = {{0,0},{0,0},{0,0},{0,0}};
#pragma unroll
        for (int c = 0; c < 4; c++) {
#pragma unroll 8
            for (int kk = 0; kk < 32; kk++) {
                float2 wv = Ws[(c * 32 + kk) * 32 + l];
#pragma unroll
                for (int r = 0; r < 4; r++) {
                    float xv = __shfl_sync(0xffffffffu, xr[r][c], kk);
                    acc[r].x += xv * wv.x;
                    acc[r].y += xv * wv.y;
                }
            }
        }
#pragma unroll
        for (int r = 0; r < 4; r++) {
            int row = row0 + r;
            if (row >= n) break;
            ((float2*)(d_h1 + (size_t)row * 64))[l] = acc[r];
            float ps = acc[r].x * atts[2 * l] + acc[r].y * atts[2 * l + 1];
            float pd = acc[r].x * attd[2 * l] + acc[r].y * attd[2 * l + 1];
            ps += __shfl_xor_sync(0xffffffffu, ps, 1);
            ps += __shfl_xor_sync(0xffffffffu, ps, 2);
            pd += __shfl_xor_sync(0xffffffffu, pd, 1);
            pd += __shfl_xor_sync(0xffffffffu, pd, 2);
            if ((l & 3) == 0) {
                d_as1[row * 8 + (l >> 2)] = ps;
                d_ad1[row * 8 + (l >> 2)] = pd;
            }
        }
    }
}

// --------------------------- Layer 1 aggregate ---------------------------
// warp per dst node; lane l owns x1 channels 2l,2l+1 (head = l>>2).
// Epilogue: ELU + layer2 logits a_src2/a_dst2 = x1 . (W2 @ att2).
__global__ __launch_bounds__(256) void k_agg1(const float* __restrict__ bias1, int n) {
    int t = threadIdx.x, w = t >> 5, l = t & 31;
    int node = blockIdx.x * 8 + w;
    if (node >= n) return;
    int hl = l >> 2;
    float adv = d_ad1[node * 8 + (l & 7)];
    int beg = d_off[node], end = d_off[node + 1];
    float acc0 = 0.f, acc1 = 0.f, dsum = 0.f;
    for (int ch = beg; ch < end; ch += 32) {
        int cnt = end - ch;
        int idx = d_ssrc[min(ch + l, end - 1)];
        float ec[8];
#pragma unroll
        for (int g = 0; g < 8; g++) {
            int ka = g * 4 + (l >> 3);
            int sA = __shfl_sync(0xffffffffu, idx, g * 4 + (l >> 3));
            float e = 0.f;
            if (ka < cnt) {
                float al = __ldg(&d_as1[sA * 8 + (l & 7)]) + adv;
                al = (al >= 0.f) ? al : 0.2f * al;
                e = __expf(al);
            }
            ec[g] = e;
        }
#pragma unroll
        for (int g8 = 0; g8 < 4; g8++) {
            if (g8 * 8 >= cnt) break;
            int sj[8];
#pragma unroll
            for (int j = 0; j < 8; j++)
                sj[j] = __shfl_sync(0xffffffffu, idx, g8 * 8 + j);
            float2 hj[8];
#pragma unroll
            for (int j = 0; j < 8; j++)
                hj[j] = ((const float2*)(d_h1 + (size_t)sj[j] * 64))[l];
            float ev[8];
#pragma unroll
            for (int j = 0; j < 8; j++)
                ev[j] = __shfl_sync(0xffffffffu, ec[g8 * 2 + (j >> 2)], (j & 3) * 8 + hl);
#pragma unroll
            for (int j = 0; j < 8; j++) {
                acc0 += ev[j] * hj[j].x;
                acc1 += ev[j] * hj[j].y;
                dsum += ev[j];
            }
        }
    }
    float inv = 1.f / (dsum + 1e-16f);
    float o0 = acc0 * inv + bias1[2 * l];
    float o1 = acc1 * inv + bias1[2 * l + 1];
    o0 = (o0 > 0.f) ? o0 : expm1f(o0);
    o1 = (o1 > 0.f) ? o1 : expm1f(o1);
    ((float2*)(d_x1 + (size_t)node * 64))[l] = make_float2(o0, o1);
    float ss = o0 * d_wsrc[2 * l] + o1 * d_wsrc[2 * l + 1];
    float sd = o0 * d_wdst[2 * l] + o1 * d_wdst[2 * l + 1];
#pragma unroll
    for (int o = 16; o; o >>= 1) {
        ss += __shfl_xor_sync(0xffffffffu, ss, o);
        sd += __shfl_xor_sync(0xffffffffu, sd, o);
    }
    if (l == 0) { d_as2[node] = ss; d_ad2[node] = sd; }
}

// ------------- Layer 2 aggregate FUSED with final GEMM -------------------
// z[node] = softmax-weighted sum of x1[src]; out[node] = z @ W2 + b2.
// The GEMM FMAs hide under the gather latency.
__global__ __launch_bounds__(256) void k_agg2F(
    const float* __restrict__ W2, const float* __restrict__ bias2,
    float* __restrict__ out, int n)
{
    __shared__ float4 Ws[64 * 32];   // Ws[k*32+l] = W2[k][4l..4l+3]
    __shared__ float4 bs[32];
    int t = threadIdx.x, w = t >> 5, l = t & 31;
    const float4* Wv = (const float4*)W2;
    for (int i = t; i < 2048; i += 256) Ws[i] = Wv[i];
    if (t < 32) bs[t] = ((const float4*)bias2)[t];
    __syncthreads();
    int node = blockIdx.x * 8 + w;
    if (node >= n) return;
    float adv = d_ad2[node];
    int beg = d_off[node], end = d_off[node + 1];
    float a0 = 0.f, a1 = 0.f, dpart = 0.f;
    for (int ch = beg; ch < end; ch += 32) {
        int cnt = end - ch;
        int idx = d_ssrc[min(ch + l, end - 1)];
        float e = 0.f;
        if (l < cnt) {
            float al = __ldg(&d_as2[idx]) + adv;
            al = (al >= 0.f) ? al : 0.2f * al;
            e = __expf(al);
            dpart += e;
        }
#pragma unroll
        for (int g8 = 0; g8 < 4; g8++) {
            if (g8 * 8 >= cnt) break;
            int sj[8];
            float ej[8];
#pragma unroll
            for (int j = 0; j < 8; j++) {
                sj[j] = __shfl_sync(0xffffffffu, idx, g8 * 8 + j);
                ej[j] = __shfl_sync(0xffffffffu, e,   g8 * 8 + j);
            }
            float2 hj[8];
#pragma unroll
            for (int j = 0; j < 8; j++)
                hj[j] = ((const float2*)(d_x1 + (size_t)sj[j] * 64))[l];
#pragma unroll
            for (int j = 0; j < 8; j++) {
                a0 += ej[j] * hj[j].x;
                a1 += ej[j] * hj[j].y;
            }
        }
    }
#pragma unroll
    for (int o = 16; o; o >>= 1) dpart += __shfl_xor_sync(0xffffffffu, dpart, o);
    float inv = 1.f / (dpart + 1e-16f);
    float z0 = a0 * inv, z1 = a1 * inv;   // lane l holds z[2l], z[2l+1]
    // out[node] = z @ W2 + b2 ; lane l owns output cols 4l..4l+3
    float4 acc = make_float4(0.f, 0.f, 0.f, 0.f);
#pragma unroll
    for (int k = 0; k < 64; k++) {
        float xv = __shfl_sync(0xffffffffu, (k & 1) ? z1 : z0, k >> 1);
        float4 wv = Ws[k * 32 + l];
        acc.x += xv * wv.x; acc.y += xv * wv.y;
        acc.z += xv * wv.z; acc.w += xv * wv.w;
    }
    float4 b = bs[l];
    ((float4*)(out + (size_t)node * 128))[l] =
        make_float4(acc.x + b.x, acc.y + b.y, acc.z + b.z, acc.w + b.w);
}

// ------------------------------- launch ----------------------------------
extern "C" void kernel_launch(void* const* d_in, const int* in_sizes, int n_in,
                              void* d_out, int out_size)
{
    const float* x    = (const float*)d_in[0];
    const int*   ei   = (const int*)d_in[1];
    const float* W1   = (const float*)d_in[2];
    const float* asr1 = (const float*)d_in[3];
    const float* ads1 = (const float*)d_in[4];
    const float* b1   = (const float*)d_in[5];
    const float* W2   = (const float*)d_in[6];
    const float* asr2 = (const float*)d_in[7];
    const float* ads2 = (const float*)d_in[8];
    const float* b2   = (const float*)d_in[9];
    float* out = (float*)d_out;

    int N  = in_sizes[0] / 128;
    int E  = in_sizes[1] / 2;
    int vec = ((E & 3) == 0) ? 1 : 0;
    int e4 = (E + 3) / 4;

    k_hist<<<(e4 + 255) / 256, 256>>>(ei, E, vec, W2, asr2, ads2);
    k_scan<<<1, 1024>>>(N);

    int ntb = ((N + 3) / 4 + 7) / 8;
    int sb  = (e4 + 255) / 256;
    int G   = 2 * (ntb > sb ? ntb : sb);
    k_gemm1_scatter<<<G, 256>>>(x, W1, asr1, ads1, N, ei, E, vec);

    k_agg1<<<(N + 7) / 8, 256>>>(b1, N);
    k_agg2F<<<(N + 7) / 8, 256>>>(W2, b2, out, N);
}

// round 9
// speedup vs baseline: 1.0232x; 1.0232x over previous
#include <cuda_runtime.h>
#include <math.h>

#define MAXN 50048
#define MAXE 1650080

// ------------ static device scratch (zero-initialized at load) -----------
__device__ float d_h1[MAXN * 64];
__device__ float d_as1[MAXN * 8];
__device__ float d_ad1[MAXN * 8];
__device__ float d_x1[MAXN * 64];
__device__ float d_as2[MAXN];
__device__ float d_ad2[MAXN];
__device__ float d_wsrc[64];
__device__ float d_wdst[64];
__device__ int   d_deg[MAXN];      // zero at load; k_scan re-zeroes after use
__device__ int   d_off[MAXN + 1];
__device__ int   d_cur[MAXN];
__device__ int   d_ssrc[MAXE];

// ---------------- hist (+ block0 computes wsrc/wdst = W2 @ att2) ----------
__global__ void k_hist(const int* __restrict__ ei, int E, int vec,
                       const float* __restrict__ W2,
                       const float* __restrict__ as2v, const float* __restrict__ ad2v) {
    if (blockIdx.x == 0 && threadIdx.x < 128) {
        int k = threadIdx.x & 63;
        const float* att = (threadIdx.x < 64) ? as2v : ad2v;
        float s = 0.f;
#pragma unroll 16
        for (int c = 0; c < 128; c++) s += W2[k * 128 + c] * att[c];
        if (threadIdx.x < 64) d_wsrc[k] = s;
        else                  d_wdst[k] = s;
    }
    int i = blockIdx.x * blockDim.x + threadIdx.x;
    int e = i * 4;
    if (e >= E) return;
    if (vec && e + 3 < E) {
        int4 d = *(const int4*)(ei + E + e);
        atomicAdd(&d_deg[d.x], 1);
        atomicAdd(&d_deg[d.y], 1);
        atomicAdd(&d_deg[d.z], 1);
        atomicAdd(&d_deg[d.w], 1);
    } else {
        for (int j = e; j < E && j < e + 4; j++)
            atomicAdd(&d_deg[ei[E + j]], 1);
    }
}

// single-block scan; places self loop at slot 0; re-zeroes d_deg
__global__ __launch_bounds__(1024) void k_scan(int n) {
    __shared__ int warpsum[32];
    int t = threadIdx.x, lane = t & 31, wid = t >> 5;
    int ipt = (n + 1023) >> 10;
    int start = t * ipt;
    int endi  = min(start + ipt, n);
    int s = 0;
    for (int i = start; i < endi; i++) s += d_deg[i] + 1;
    int incl = s;
#pragma unroll
    for (int o = 1; o < 32; o <<= 1) {
        int v = __shfl_up_sync(0xffffffffu, incl, o);
        if (lane >= o) incl += v;
    }
    if (lane == 31) warpsum[wid] = incl;
    __syncthreads();
    if (wid == 0) {
        int v = warpsum[lane];
        int wi = v;
#pragma unroll
        for (int o = 1; o < 32; o <<= 1) {
            int u = __shfl_up_sync(0xffffffffu, wi, o);
            if (lane >= o) wi += u;
        }
        warpsum[lane] = wi - v;
    }
    __syncthreads();
    int run = warpsum[wid] + (incl - s);
    for (int i = start; i < endi; i++) {
        int d = d_deg[i];
        d_deg[i] = 0;
        d_off[i]  = run;
        d_ssrc[run] = i;
        d_cur[i]  = run + 1;
        run += d + 1;
    }
    if (t == 1023) d_off[n] = run;
}

// ------------- Fused Layer-1 GEMM + scatter (interleaved roles) -----------
__global__ __launch_bounds__(256) void k_gemm1_scatter(
    const float* __restrict__ x, const float* __restrict__ W1,
    const float* __restrict__ as, const float* __restrict__ ad, int n,
    const int* __restrict__ ei, int E, int vec)
{
    __shared__ float2 Ws[128 * 32];
    __shared__ float atts[64], attd[64];
    int t = threadIdx.x;

    if (blockIdx.x & 1) {
        int i = (blockIdx.x >> 1) * blockDim.x + t;
        int e = i * 4;
        if (e >= E) return;
        if (vec && e + 3 < E) {
            int4 s = *(const int4*)(ei + e);
            int4 d = *(const int4*)(ei + E + e);
            d_ssrc[atomicAdd(&d_cur[d.x], 1)] = s.x;
            d_ssrc[atomicAdd(&d_cur[d.y], 1)] = s.y;
            d_ssrc[atomicAdd(&d_cur[d.z], 1)] = s.z;
            d_ssrc[atomicAdd(&d_cur[d.w], 1)] = s.w;
        } else {
            for (int j = e; j < E && j < e + 4; j++)
                d_ssrc[atomicAdd(&d_cur[ei[E + j]], 1)] = ei[j];
        }
        return;
    }

    int w = t >> 5, l = t & 31;
    int nblk = gridDim.x >> 1;
    int bid  = blockIdx.x >> 1;
    const float2* Wv = (const float2*)W1;
    for (int i = t; i < 4096; i += 256) Ws[i] = Wv[i];
    if (t < 64) { atts[t] = as[t]; attd[t] = ad[t]; }
    __syncthreads();
    int ntiles = (n + 3) >> 2;
    for (int tile = bid * 8 + w; tile < ntiles; tile += nblk * 8) {
        int row0 = tile * 4;
        float xr[4][4];
#pragma unroll
        for (int r = 0; r < 4; r++) {
            const float* xp = x + (size_t)min(row0 + r, n - 1) * 128;
#pragma unroll
            for (int c = 0; c < 4; c++) xr[r][c] = xp[l + 32 * c];
        }
        float2 acc[4] = {{0,0},{0,0},{0,0},{0,0}};
#pragma unroll
        for (int c = 0; c < 4; c++) {
#pragma unroll 8
            for (int kk = 0; kk < 32; kk++) {
                float2 wv = Ws[(c * 32 + kk) * 32 + l];
#pragma unroll
                for (int r = 0; r < 4; r++) {
                    float xv = __shfl_sync(0xffffffffu, xr[r][c], kk);
                    acc[r].x += xv * wv.x;
                    acc[r].y += xv * wv.y;
                }
            }
        }
#pragma unroll
        for (int r = 0; r < 4; r++) {
            int row = row0 + r;
            if (row >= n) break;
            ((float2*)(d_h1 + (size_t)row * 64))[l] = acc[r];
            float ps = acc[r].x * atts[2 * l] + acc[r].y * atts[2 * l + 1];
            float pd = acc[r].x * attd[2 * l] + acc[r].y * attd[2 * l + 1];
            ps += __shfl_xor_sync(0xffffffffu, ps, 1);
            ps += __shfl_xor_sync(0xffffffffu, ps, 2);
            pd += __shfl_xor_sync(0xffffffffu, pd, 1);
            pd += __shfl_xor_sync(0xffffffffu, pd, 2);
            if ((l & 3) == 0) {
                d_as1[row * 8 + (l >> 2)] = ps;
                d_ad1[row * 8 + (l >> 2)] = pd;
            }
        }
    }
}

// --------------------------- Layer 1 aggregate ---------------------------
// Persistent warps: each warp loops over nodes. Lane l owns channels 2l,2l+1
// (head hl=l>>2). Denominator accumulated only in logit lanes, reduced once.
__global__ __launch_bounds__(256) void k_agg1(const float* __restrict__ bias1, int n) {
    int t = threadIdx.x, w = t >> 5, l = t & 31;
    int hl = l >> 2;
    int gw = blockIdx.x * 8 + w;
    int nw = gridDim.x * 8;
    for (int node = gw; node < n; node += nw) {
        float adv = d_ad1[node * 8 + (l & 7)];
        int beg = d_off[node], end = d_off[node + 1];
        float acc0 = 0.f, acc1 = 0.f, dloc = 0.f;
        for (int ch = beg; ch < end; ch += 32) {
            int cnt = end - ch;
            int idx = d_ssrc[min(ch + l, end - 1)];
            float ec[8];
#pragma unroll
            for (int g = 0; g < 8; g++) {
                int ka = g * 4 + (l >> 3);
                int sA = __shfl_sync(0xffffffffu, idx, g * 4 + (l >> 3));
                float e = 0.f;
                if (ka < cnt) {
                    float al = __ldg(&d_as1[sA * 8 + (l & 7)]) + adv;
                    al = (al >= 0.f) ? al : 0.2f * al;
                    e = __expf(al);
                }
                ec[g] = e;
                dloc += e;
            }
#pragma unroll
            for (int g8 = 0; g8 < 4; g8++) {
                if (g8 * 8 >= cnt) break;
                int sj[8];
#pragma unroll
                for (int j = 0; j < 8; j++)
                    sj[j] = __shfl_sync(0xffffffffu, idx, g8 * 8 + j);
                float2 hj[8];
#pragma unroll
                for (int j = 0; j < 8; j++)
                    hj[j] = ((const float2*)(d_h1 + (size_t)sj[j] * 64))[l];
                float ev[8];
#pragma unroll
                for (int j = 0; j < 8; j++)
                    ev[j] = __shfl_sync(0xffffffffu, ec[g8 * 2 + (j >> 2)], (j & 3) * 8 + hl);
#pragma unroll
                for (int j = 0; j < 8; j++) {
                    acc0 += ev[j] * hj[j].x;
                    acc1 += ev[j] * hj[j].y;
                }
            }
        }
        // denominator: lane l holds partial sum for head l&7 over edges l>>3 (mod 4)
        dloc += __shfl_xor_sync(0xffffffffu, dloc, 8);
        dloc += __shfl_xor_sync(0xffffffffu, dloc, 16);
        float dsum = __shfl_sync(0xffffffffu, dloc, hl);   // lane hl holds head hl
        float inv = 1.f / (dsum + 1e-16f);
        float o0 = acc0 * inv + bias1[2 * l];
        float o1 = acc1 * inv + bias1[2 * l + 1];
        o0 = (o0 > 0.f) ? o0 : expm1f(o0);
        o1 = (o1 > 0.f) ? o1 : expm1f(o1);
        ((float2*)(d_x1 + (size_t)node * 64))[l] = make_float2(o0, o1);
        float ss = o0 * d_wsrc[2 * l] + o1 * d_wsrc[2 * l + 1];
        float sd = o0 * d_wdst[2 * l] + o1 * d_wdst[2 * l + 1];
#pragma unroll
        for (int o = 16; o; o >>= 1) {
            ss += __shfl_xor_sync(0xffffffffu, ss, o);
            sd += __shfl_xor_sync(0xffffffffu, sd, o);
        }
        if (l == 0) { d_as2[node] = ss; d_ad2[node] = sd; }
    }
}

// ------------- Layer 2 aggregate FUSED with final GEMM (persistent) -------
// z = softmax-weighted sum of x1[src]; out = z @ W2 + b2. W2 loaded once/block.
__global__ __launch_bounds__(256) void k_agg2F(
    const float* __restrict__ W2, const float* __restrict__ bias2,
    float* __restrict__ out, int n)
{
    __shared__ float4 Ws[64 * 32];   // Ws[k*32+l] = W2[k][4l..4l+3]
    __shared__ float4 bs[32];
    int t = threadIdx.x, w = t >> 5, l = t & 31;
    const float4* Wv = (const float4*)W2;
    for (int i = t; i < 2048; i += 256) Ws[i] = Wv[i];
    if (t < 32) bs[t] = ((const float4*)bias2)[t];
    __syncthreads();
    int gw = blockIdx.x * 8 + w;
    int nw = gridDim.x * 8;
    for (int node = gw; node < n; node += nw) {
        float adv = d_ad2[node];
        int beg = d_off[node], end = d_off[node + 1];
        float a0 = 0.f, a1 = 0.f, dpart = 0.f;
        for (int ch = beg; ch < end; ch += 32) {
            int cnt = end - ch;
            int idx = d_ssrc[min(ch + l, end - 1)];
            float e = 0.f;
            if (l < cnt) {
                float al = __ldg(&d_as2[idx]) + adv;
                al = (al >= 0.f) ? al : 0.2f * al;
                e = __expf(al);
                dpart += e;
            }
#pragma unroll
            for (int g8 = 0; g8 < 4; g8++) {
                if (g8 * 8 >= cnt) break;
                int sj[8];
                float ej[8];
#pragma unroll
                for (int j = 0; j < 8; j++) {
                    sj[j] = __shfl_sync(0xffffffffu, idx, g8 * 8 + j);
                    ej[j] = __shfl_sync(0xffffffffu, e,   g8 * 8 + j);
                }
                float2 hj[8];
#pragma unroll
                for (int j = 0; j < 8; j++)
                    hj[j] = ((const float2*)(d_x1 + (size_t)sj[j] * 64))[l];
#pragma unroll
                for (int j = 0; j < 8; j++) {
                    a0 += ej[j] * hj[j].x;
                    a1 += ej[j] * hj[j].y;
                }
            }
        }
#pragma unroll
        for (int o = 16; o; o >>= 1) dpart += __shfl_xor_sync(0xffffffffu, dpart, o);
        float inv = 1.f / (dpart + 1e-16f);
        float z0 = a0 * inv, z1 = a1 * inv;   // lane l holds z[2l], z[2l+1]
        float4 acc = make_float4(0.f, 0.f, 0.f, 0.f);
#pragma unroll
        for (int k = 0; k < 64; k++) {
            float xv = __shfl_sync(0xffffffffu, (k & 1) ? z1 : z0, k >> 1);
            float4 wv = Ws[k * 32 + l];
            acc.x += xv * wv.x; acc.y += xv * wv.y;
            acc.z += xv * wv.z; acc.w += xv * wv.w;
        }
        float4 b = bs[l];
        ((float4*)(out + (size_t)node * 128))[l] =
            make_float4(acc.x + b.x, acc.y + b.y, acc.z + b.z, acc.w + b.w);
    }
}

// ------------------------------- launch ----------------------------------
extern "C" void kernel_launch(void* const* d_in, const int* in_sizes, int n_in,
                              void* d_out, int out_size)
{
    const float* x    = (const float*)d_in[0];
    const int*   ei   = (const int*)d_in[1];
    const float* W1   = (const float*)d_in[2];
    const float* asr1 = (const float*)d_in[3];
    const float* ads1 = (const float*)d_in[4];
    const float* b1   = (const float*)d_in[5];
    const float* W2   = (const float*)d_in[6];
    const float* asr2 = (const float*)d_in[7];
    const float* ads2 = (const float*)d_in[8];
    const float* b2   = (const float*)d_in[9];
    float* out = (float*)d_out;

    int N  = in_sizes[0] / 128;
    int E  = in_sizes[1] / 2;
    int vec = ((E & 3) == 0) ? 1 : 0;
    int e4 = (E + 3) / 4;

    k_hist<<<(e4 + 255) / 256, 256>>>(ei, E, vec, W2, asr2, ads2);
    k_scan<<<1, 1024>>>(N);

    int ntb = ((N + 3) / 4 + 7) / 8;
    int sb  = (e4 + 255) / 256;
    int G   = 2 * (ntb > sb ? ntb : sb);
    k_gemm1_scatter<<<G, 256>>>(x, W1, asr1, ads1, N, ei, E, vec);

    k_agg1<<<1184, 256>>>(b1, N);
    k_agg2F<<<1184, 256>>>(W2, b2, out, N);
}

// round 10
// speedup vs baseline: 1.0948x; 1.0700x over previous
#include <cuda_runtime.h>
#include <math.h>

#define MAXN 50048
#define MAXE 1650080

// ------------ static device scratch (zero-initialized at load) -----------
__device__ float d_h1[MAXN * 64];
__device__ float d_as1[MAXN * 8];
__device__ float d_ad1[MAXN * 8];
__device__ float d_x1[MAXN * 64];
__device__ float d_z[MAXN * 64];
__device__ float d_as2[MAXN];
__device__ float d_ad2[MAXN];
__device__ float d_wsrc[64];
__device__ float d_wdst[64];
__device__ int   d_deg[MAXN];      // zero at load; k_scan re-zeroes after use
__device__ int   d_off[MAXN + 1];
__device__ int   d_cur[MAXN];
__device__ int   d_ssrc[MAXE];

// ---------------- hist (+ block0 computes wsrc/wdst = W2 @ att2) ----------
__global__ void k_hist(const int* __restrict__ ei, int E, int vec,
                       const float* __restrict__ W2,
                       const float* __restrict__ as2v, const float* __restrict__ ad2v) {
    if (blockIdx.x == 0 && threadIdx.x < 128) {
        int k = threadIdx.x & 63;
        const float* att = (threadIdx.x < 64) ? as2v : ad2v;
        float s = 0.f;
#pragma unroll 16
        for (int c = 0; c < 128; c++) s += W2[k * 128 + c] * att[c];
        if (threadIdx.x < 64) d_wsrc[k] = s;
        else                  d_wdst[k] = s;
    }
    int i = blockIdx.x * blockDim.x + threadIdx.x;
    int e = i * 4;
    if (e >= E) return;
    if (vec && e + 3 < E) {
        int4 d = *(const int4*)(ei + E + e);
        atomicAdd(&d_deg[d.x], 1);
        atomicAdd(&d_deg[d.y], 1);
        atomicAdd(&d_deg[d.z], 1);
        atomicAdd(&d_deg[d.w], 1);
    } else {
        for (int j = e; j < E && j < e + 4; j++)
            atomicAdd(&d_deg[ei[E + j]], 1);
    }
}

// single-block scan; places self loop at slot 0; re-zeroes d_deg
__global__ __launch_bounds__(1024) void k_scan(int n) {
    __shared__ int warpsum[32];
    int t = threadIdx.x, lane = t & 31, wid = t >> 5;
    int ipt = (n + 1023) >> 10;
    int start = t * ipt;
    int endi  = min(start + ipt, n);
    int s = 0;
    for (int i = start; i < endi; i++) s += d_deg[i] + 1;
    int incl = s;
#pragma unroll
    for (int o = 1; o < 32; o <<= 1) {
        int v = __shfl_up_sync(0xffffffffu, incl, o);
        if (lane >= o) incl += v;
    }
    if (lane == 31) warpsum[wid] = incl;
    __syncthreads();
    if (wid == 0) {
        int v = warpsum[lane];
        int wi = v;
#pragma unroll
        for (int o = 1; o < 32; o <<= 1) {
            int u = __shfl_up_sync(0xffffffffu, wi, o);
            if (lane >= o) wi += u;
        }
        warpsum[lane] = wi - v;
    }
    __syncthreads();
    int run = warpsum[wid] + (incl - s);
    for (int i = start; i < endi; i++) {
        int d = d_deg[i];
        d_deg[i] = 0;
        d_off[i]  = run;
        d_ssrc[run] = i;
        d_cur[i]  = run + 1;
        run += d + 1;
    }
    if (t == 1023) d_off[n] = run;
}

// ------------- Fused Layer-1 GEMM + scatter (interleaved roles) -----------
__global__ __launch_bounds__(256) void k_gemm1_scatter(
    const float* __restrict__ x, const float* __restrict__ W1,
    const float* __restrict__ as, const float* __restrict__ ad, int n,
    const int* __restrict__ ei, int E, int vec)
{
    __shared__ float2 Ws[128 * 32];
    __shared__ float atts[64], attd[64];
    int t = threadIdx.x;

    if (blockIdx.x & 1) {
        int i = (blockIdx.x >> 1) * blockDim.x + t;
        int e = i * 4;
        if (e >= E) return;
        if (vec && e + 3 < E) {
            int4 s = *(const int4*)(ei + e);
            int4 d = *(const int4*)(ei + E + e);
            d_ssrc[atomicAdd(&d_cur[d.x], 1)] = s.x;
            d_ssrc[atomicAdd(&d_cur[d.y], 1)] = s.y;
            d_ssrc[atomicAdd(&d_cur[d.z], 1)] = s.z;
            d_ssrc[atomicAdd(&d_cur[d.w], 1)] = s.w;
        } else {
            for (int j = e; j < E && j < e + 4; j++)
                d_ssrc[atomicAdd(&d_cur[ei[E + j]], 1)] = ei[j];
        }
        return;
    }

    int w = t >> 5, l = t & 31;
    int nblk = gridDim.x >> 1;
    int bid  = blockIdx.x >> 1;
    const float2* Wv = (const float2*)W1;
    for (int i = t; i < 4096; i += 256) Ws[i] = Wv[i];
    if (t < 64) { atts[t] = as[t]; attd[t] = ad[t]; }
    __syncthreads();
    int ntiles = (n + 3) >> 2;
    for (int tile = bid * 8 + w; tile < ntiles; tile += nblk * 8) {
        int row0 = tile * 4;
        float xr[4][4];
#pragma unroll
        for (int r = 0; r < 4; r++) {
            const float* xp = x + (size_t)min(row0 + r, n - 1) * 128;
#pragma unroll
            for (int c = 0; c < 4; c++) xr[r][c] = xp[l + 32 * c];
        }
        float2 acc[4] = {{0,0},{0,0},{0,0},{0,0}};
#pragma unroll
        for (int c = 0; c < 4; c++) {
#pragma unroll 8
            for (int kk = 0; kk < 32; kk++) {
                float2 wv = Ws[(c * 32 + kk) * 32 + l];
#pragma unroll
                for (int r = 0; r < 4; r++) {
                    float xv = __shfl_sync(0xffffffffu, xr[r][c], kk);
                    acc[r].x += xv * wv.x;
                    acc[r].y += xv * wv.y;
                }
            }
        }
#pragma unroll
        for (int r = 0; r < 4; r++) {
            int row = row0 + r;
            if (row >= n) break;
            ((float2*)(d_h1 + (size_t)row * 64))[l] = acc[r];
            float ps = acc[r].x * atts[2 * l] + acc[r].y * atts[2 * l + 1];
            float pd = acc[r].x * attd[2 * l] + acc[r].y * attd[2 * l + 1];
            ps += __shfl_xor_sync(0xffffffffu, ps, 1);
            ps += __shfl_xor_sync(0xffffffffu, ps, 2);
            pd += __shfl_xor_sync(0xffffffffu, pd, 1);
            pd += __shfl_xor_sync(0xffffffffu, pd, 2);
            if ((l & 3) == 0) {
                d_as1[row * 8 + (l >> 2)] = ps;
                d_ad1[row * 8 + (l >> 2)] = pd;
            }
        }
    }
}

// --------------------------- Layer 1 aggregate ---------------------------
// Persistent warps; lane l owns channels 2l,2l+1 (head hl=l>>2).
__global__ __launch_bounds__(256) void k_agg1(const float* __restrict__ bias1, int n) {
    int t = threadIdx.x, w = t >> 5, l = t & 31;
    int hl = l >> 2;
    int gw = blockIdx.x * 8 + w;
    int nw = gridDim.x * 8;
    for (int node = gw; node < n; node += nw) {
        float adv = d_ad1[node * 8 + (l & 7)];
        int beg = d_off[node], end = d_off[node + 1];
        float acc0 = 0.f, acc1 = 0.f, dloc = 0.f;
        for (int ch = beg; ch < end; ch += 32) {
            int cnt = end - ch;
            int idx = d_ssrc[min(ch + l, end - 1)];
            float ec[8];
#pragma unroll
            for (int g = 0; g < 8; g++) {
                int ka = g * 4 + (l >> 3);
                int sA = __shfl_sync(0xffffffffu, idx, g * 4 + (l >> 3));
                float e = 0.f;
                if (ka < cnt) {
                    float al = __ldg(&d_as1[sA * 8 + (l & 7)]) + adv;
                    al = (al >= 0.f) ? al : 0.2f * al;
                    e = __expf(al);
                }
                ec[g] = e;
                dloc += e;
            }
#pragma unroll
            for (int g8 = 0; g8 < 4; g8++) {
                if (g8 * 8 >= cnt) break;
                int sj[8];
#pragma unroll
                for (int j = 0; j < 8; j++)
                    sj[j] = __shfl_sync(0xffffffffu, idx, g8 * 8 + j);
                float2 hj[8];
#pragma unroll
                for (int j = 0; j < 8; j++)
                    hj[j] = ((const float2*)(d_h1 + (size_t)sj[j] * 64))[l];
                float ev[8];
#pragma unroll
                for (int j = 0; j < 8; j++)
                    ev[j] = __shfl_sync(0xffffffffu, ec[g8 * 2 + (j >> 2)], (j & 3) * 8 + hl);
#pragma unroll
                for (int j = 0; j < 8; j++) {
                    acc0 += ev[j] * hj[j].x;
                    acc1 += ev[j] * hj[j].y;
                }
            }
        }
        dloc += __shfl_xor_sync(0xffffffffu, dloc, 8);
        dloc += __shfl_xor_sync(0xffffffffu, dloc, 16);
        float dsum = __shfl_sync(0xffffffffu, dloc, hl);
        float inv = 1.f / (dsum + 1e-16f);
        float o0 = acc0 * inv + bias1[2 * l];
        float o1 = acc1 * inv + bias1[2 * l + 1];
        o0 = (o0 > 0.f) ? o0 : expm1f(o0);
        o1 = (o1 > 0.f) ? o1 : expm1f(o1);
        ((float2*)(d_x1 + (size_t)node * 64))[l] = make_float2(o0, o1);
        float ss = o0 * d_wsrc[2 * l] + o1 * d_wsrc[2 * l + 1];
        float sd = o0 * d_wdst[2 * l] + o1 * d_wdst[2 * l + 1];
#pragma unroll
        for (int o = 16; o; o >>= 1) {
            ss += __shfl_xor_sync(0xffffffffu, ss, o);
            sd += __shfl_xor_sync(0xffffffffu, sd, o);
        }
        if (l == 0) { d_as2[node] = ss; d_ad2[node] = sd; }
    }
}

// --------------------------- Layer 2 aggregate ---------------------------
// TWO nodes per warp: lanes 0-15 -> node A, 16-31 -> node B. Lane owns
// channels 4*hl..4*hl+3 of its node's z row. One warp-LDG serves 2 edges.
// Halves kept convergent: iterate max(chunks) with predicated (e=0) edges.
__global__ __launch_bounds__(256) void k_agg2(int n) {
    int t = threadIdx.x, w = t >> 5, l = t & 31;
    int half = l >> 4, hl = l & 15;
    unsigned hmask = 0xFFFFu << (half * 16);
    int gp = blockIdx.x * 8 + w;           // pair index
    int np = gridDim.x * 8;
    int npairs = (n + 1) >> 1;
    for (int pair = gp; pair < npairs; pair += np) {
        int node = pair * 2 + half;
        bool act = node < n;
        int beg = act ? d_off[node]     : 0;
        int end = act ? d_off[node + 1] : 1;
        float adv = act ? d_ad2[node] : 0.f;
        int nIt = (end - beg + 15) >> 4;
        // warp-uniform iteration count
        int nOther = __shfl_xor_sync(0xffffffffu, nIt, 16);
        int nMax = max(nIt, nOther);
        float4 acc = make_float4(0.f, 0.f, 0.f, 0.f);
        float dloc = 0.f;
        for (int it = 0; it < nMax; it++) {
            int ch = beg + it * 16;
            int cnt = end - ch;                       // may be <=0 for shorter half
            int idx = d_ssrc[max(min(ch + hl, end - 1), beg)];
            float e = 0.f;
            if (hl < cnt) {
                float al = __ldg(&d_as2[idx]) + adv;
                al = (al >= 0.f) ? al : 0.2f * al;
                e = __expf(al);
                dloc += e;
            }
            int cntO = __shfl_xor_sync(0xffffffffu, cnt, 16);
            int cntM = max(cnt, cntO);                // warp-uniform break bound
#pragma unroll
            for (int g4 = 0; g4 < 4; g4++) {
                if (g4 * 4 >= cntM) break;
                int sj[4];
                float ej[4];
#pragma unroll
                for (int j = 0; j < 4; j++) {
                    sj[j] = __shfl_sync(0xffffffffu, idx, g4 * 4 + j, 16);
                    ej[j] = __shfl_sync(0xffffffffu, e,   g4 * 4 + j, 16);
                }
                float4 hj[4];
#pragma unroll
                for (int j = 0; j < 4; j++)
                    hj[j] = ((const float4*)(d_x1 + (size_t)sj[j] * 64))[hl];
#pragma unroll
                for (int j = 0; j < 4; j++) {
                    acc.x += ej[j] * hj[j].x; acc.y += ej[j] * hj[j].y;
                    acc.z += ej[j] * hj[j].z; acc.w += ej[j] * hj[j].w;
                }
            }
        }
        // denominator reduce within the 16-lane half
        dloc += __shfl_xor_sync(hmask, dloc, 1, 16);
        dloc += __shfl_xor_sync(hmask, dloc, 2, 16);
        dloc += __shfl_xor_sync(hmask, dloc, 4, 16);
        dloc += __shfl_xor_sync(hmask, dloc, 8, 16);
        float inv = 1.f / (dloc + 1e-16f);
        if (act) {
            ((float4*)(d_z + (size_t)node * 64))[hl] =
                make_float4(acc.x * inv, acc.y * inv, acc.z * inv, acc.w * inv);
        }
    }
}

// ---------------------- Final GEMM: out = z @ W2 + b2 --------------------
__global__ __launch_bounds__(256) void k_gemmF(
    const float* __restrict__ W2, const float* __restrict__ bias2,
    float* __restrict__ out, int n)
{
    __shared__ float4 Ws[64 * 32];
    __shared__ float4 bs[32];
    int t = threadIdx.x, w = t >> 5, l = t & 31;
    const float4* Wv = (const float4*)W2;
    for (int i = t; i < 2048; i += 256) Ws[i] = Wv[i];
    if (t < 32) bs[t] = ((const float4*)bias2)[t];
    __syncthreads();
    int ntiles = (n + 3) >> 2;
    for (int tile = blockIdx.x * 8 + w; tile < ntiles; tile += gridDim.x * 8) {
        int row0 = tile * 4;
        float xr[4][2];
#pragma unroll
        for (int r = 0; r < 4; r++) {
            const float* xp = d_z + (size_t)min(row0 + r, n - 1) * 64;
#pragma unroll
            for (int c = 0; c < 2; c++) xr[r][c] = xp[l + 32 * c];
        }
        float4 acc[4] = {{0,0,0,0},{0,0,0,0},{0,0,0,0},{0,0,0,0}};
#pragma unroll
        for (int c = 0; c < 2; c++) {
#pragma unroll 8
            for (int kk = 0; kk < 32; kk++) {
                float4 wv = Ws[(c * 32 + kk) * 32 + l];
#pragma unroll
                for (int r = 0; r < 4; r++) {
                    float xv = __shfl_sync(0xffffffffu, xr[r][c], kk);
                    acc[r].x += xv * wv.x; acc[r].y += xv * wv.y;
                    acc[r].z += xv * wv.z; acc[r].w += xv * wv.w;
                }
            }
        }
        float4 b = bs[l];
#pragma unroll
        for (int r = 0; r < 4; r++) {
            int row = row0 + r;
            if (row >= n) break;
            ((float4*)(out + (size_t)row * 128))[l] =
                make_float4(acc[r].x + b.x, acc[r].y + b.y,
                            acc[r].z + b.z, acc[r].w + b.w);
        }
    }
}

// ------------------------------- launch ----------------------------------
extern "C" void kernel_launch(void* const* d_in, const int* in_sizes, int n_in,
                              void* d_out, int out_size)
{
    const float* x    = (const float*)d_in[0];
    const int*   ei   = (const int*)d_in[1];
    const float* W1   = (const float*)d_in[2];
    const float* asr1 = (const float*)d_in[3];
    const float* ads1 = (const float*)d_in[4];
    const float* b1   = (const float*)d_in[5];
    const float* W2   = (const float*)d_in[6];
    const float* asr2 = (const float*)d_in[7];
    const float* ads2 = (const float*)d_in[8];
    const float* b2   = (const float*)d_in[9];
    float* out = (float*)d_out;

    int N  = in_sizes[0] / 128;
    int E  = in_sizes[1] / 2;
    int vec = ((E & 3) == 0) ? 1 : 0;
    int e4 = (E + 3) / 4;

    k_hist<<<(e4 + 255) / 256, 256>>>(ei, E, vec, W2, asr2, ads2);
    k_scan<<<1, 1024>>>(N);

    int ntb = ((N + 3) / 4 + 7) / 8;
    int sb  = (e4 + 255) / 256;
    int G   = 2 * (ntb > sb ? ntb : sb);
    k_gemm1_scatter<<<G, 256>>>(x, W1, asr1, ads1, N, ei, E, vec);

    k_agg1<<<1184, 256>>>(b1, N);
    k_agg2<<<1184, 256>>>(N);
    k_gemmF<<<ntb, 256>>>(W2, b2, out, N);
}